// round 4
// baseline (speedup 1.0000x reference)
#include <cuda_runtime.h>
#include <cuda_bf16.h>
#include <cstdint>
#include <cstddef>

// ============================================================================
// Problem dims
// ============================================================================
#define MM 8192
#define KK 4096
#define NN 4096

// ============================================================================
// Device scratch (allowed: __device__ globals, no runtime allocation)
// ============================================================================
__device__ unsigned g_amax_x;
__device__ unsigned g_amax_w;
__device__ int8_t g_xq[(size_t)MM * KK];   // quantized activations
__device__ int8_t g_wq[(size_t)NN * KK];   // quantized weights

// ============================================================================
// PTX helpers — family-generic (sm_80+ PTX only; NO tcgen05 on this target!)
// ============================================================================
__device__ __forceinline__ uint32_t smem_u32(const void* p) {
    uint32_t a;
    asm("{ .reg .u64 t; cvta.to.shared.u64 t, %1; cvt.u32.u64 %0, t; }" : "=r"(a) : "l"(p));
    return a;
}

#define CP_ASYNC16(dst, src) \
    asm volatile("cp.async.cg.shared.global [%0], [%1], 16;" :: "r"(dst), "l"(src) : "memory")
#define CP_COMMIT() asm volatile("cp.async.commit_group;" ::: "memory")
#define CP_WAIT2()  asm volatile("cp.async.wait_group 2;" ::: "memory")
#define CP_WAIT0()  asm volatile("cp.async.wait_group 0;" ::: "memory")

// int8 warp MMA: D(16x8,s32) = A(16x32,s8,row) * B(32x8,s8,col) + D
__device__ __forceinline__ void imma16832(int* c, const uint32_t* a, const uint32_t* b) {
    asm volatile(
        "mma.sync.aligned.m16n8k32.row.col.s32.s8.s8.s32 "
        "{%0,%1,%2,%3}, {%4,%5,%6,%7}, {%8,%9}, {%0,%1,%2,%3};"
        : "+r"(c[0]), "+r"(c[1]), "+r"(c[2]), "+r"(c[3])
        : "r"(a[0]), "r"(a[1]), "r"(a[2]), "r"(a[3]), "r"(b[0]), "r"(b[1]));
}

__device__ __forceinline__ uint32_t lds32(uint32_t addr) {
    uint32_t v;
    asm volatile("ld.shared.b32 %0, [%1];" : "=r"(v) : "r"(addr));
    return v;
}

// ============================================================================
// Pass 1: reset + abs-max reductions
// ============================================================================
__global__ void reset_kernel() {
    g_amax_x = 0u;
    g_amax_w = 0u;
}

__global__ void absmax_kernel(const float* __restrict__ in, long n4, int which) {
    float m = 0.0f;
    long i = (long)blockIdx.x * blockDim.x + threadIdx.x;
    long stride = (long)gridDim.x * blockDim.x;
    const float4* in4 = reinterpret_cast<const float4*>(in);
    for (; i < n4; i += stride) {
        float4 v = in4[i];
        m = fmaxf(m, fmaxf(fmaxf(fabsf(v.x), fabsf(v.y)), fmaxf(fabsf(v.z), fabsf(v.w))));
    }
    #pragma unroll
    for (int o = 16; o > 0; o >>= 1)
        m = fmaxf(m, __shfl_xor_sync(0xFFFFFFFFu, m, o));
    if ((threadIdx.x & 31) == 0)
        atomicMax(which ? &g_amax_w : &g_amax_x, __float_as_uint(m));
}

// ============================================================================
// Pass 2: quantize — exact match to jnp: clip(rint(t/scale), ±127) -> int8
// ============================================================================
__global__ void quant_kernel(const float* __restrict__ in, long n4, int which) {
    float amax = __uint_as_float(which ? g_amax_w : g_amax_x);
    float scale = amax / 127.0f;
    int8_t* q = which ? g_wq : g_xq;
    long i = (long)blockIdx.x * blockDim.x + threadIdx.x;
    long stride = (long)gridDim.x * blockDim.x;
    const float4* in4 = reinterpret_cast<const float4*>(in);
    char4* q4 = reinterpret_cast<char4*>(q);
    for (; i < n4; i += stride) {
        float4 v = in4[i];
        float a = fminf(fmaxf(rintf(v.x / scale), -127.0f), 127.0f);
        float b = fminf(fmaxf(rintf(v.y / scale), -127.0f), 127.0f);
        float c = fminf(fmaxf(rintf(v.z / scale), -127.0f), 127.0f);
        float d = fminf(fmaxf(rintf(v.w / scale), -127.0f), 127.0f);
        q4[i] = make_char4((signed char)a, (signed char)b, (signed char)c, (signed char)d);
    }
}

// ============================================================================
// Pass 3: int8 GEMM  out[M,N] = Xq[M,K] @ Wq[N,K]^T * s + bias
//   BM=128, BN=128, BK=64; 128 threads = 4 warps of 64x64 warp tiles
//   4-stage cp.async pipeline; SMEM rows padded 64B -> 80B (conflict-free)
// ============================================================================
static constexpr int BK = 64;
static constexpr int NKT = KK / BK;           // 64 k-tiles
static constexpr int ROW_PAD = 80;            // 64 data + 16 pad
static constexpr int A_STAGE = 128 * ROW_PAD; // 10240 B
static constexpr int STAGE_BYTES = 2 * A_STAGE; // A + B = 20480 B
static constexpr int NSTAGE = 4;
static constexpr int SMEM_BYTES = NSTAGE * STAGE_BYTES;  // 81920 B

__device__ __forceinline__ void stage_copy(uint32_t sbase, int kt, int m0, int n0, int tid) {
    const size_t kofs = (size_t)kt * BK;
    #pragma unroll
    for (int i = 0; i < 4; i++) {
        int idx = tid + i * 128;                 // 0..511
        int row = idx >> 2, ch = idx & 3;
        CP_ASYNC16(sbase + row * ROW_PAD + ch * 16,
                   (const void*)(g_xq + (size_t)(m0 + row) * KK + kofs + ch * 16));
    }
    #pragma unroll
    for (int i = 0; i < 4; i++) {
        int idx = tid + i * 128;
        int row = idx >> 2, ch = idx & 3;
        CP_ASYNC16(sbase + A_STAGE + row * ROW_PAD + ch * 16,
                   (const void*)(g_wq + (size_t)(n0 + row) * KK + kofs + ch * 16));
    }
}

extern "C" __global__ void __launch_bounds__(128, 2)
gemm_kernel(const float* __restrict__ bias, float* __restrict__ out) {
    extern __shared__ char smem[];
    const uint32_t sb = smem_u32(smem);
    const int tid = threadIdx.x;
    const int wid = tid >> 5;
    const int lane = tid & 31;
    const int warp_m = wid & 1;          // 2 warps along M
    const int warp_n = wid >> 1;         // 2 warps along N
    const int m0 = blockIdx.y * 128;
    const int n0 = blockIdx.x * 128;

    int c[4][8][4];
    #pragma unroll
    for (int mt = 0; mt < 4; mt++)
        #pragma unroll
        for (int nt = 0; nt < 8; nt++)
            #pragma unroll
            for (int j = 0; j < 4; j++) c[mt][nt][j] = 0;

    // Prologue: fill stages 0..2
    #pragma unroll
    for (int s = 0; s < NSTAGE - 1; s++) {
        stage_copy(sb + s * STAGE_BYTES, s, m0, n0, tid);
        CP_COMMIT();
    }

    const int qrow = lane >> 2;           // 0..7
    const int qcol = (lane & 3) * 4;      // byte offset within 16B group

    for (int kt = 0; kt < NKT; kt++) {
        CP_WAIT2();
        __syncthreads();

        // Issue copy for stage kt+3 (its buffer's compute finished at kt-1,
        // guaranteed by the barrier above). Commit an (empty) group each iter
        // so wait_group 2 always completes exactly stage kt.
        if (kt + NSTAGE - 1 < NKT)
            stage_copy(sb + ((kt + NSTAGE - 1) & (NSTAGE - 1)) * STAGE_BYTES,
                       kt + NSTAGE - 1, m0, n0, tid);
        CP_COMMIT();

        const uint32_t sA = sb + (kt & (NSTAGE - 1)) * STAGE_BYTES;
        const uint32_t sB = sA + A_STAGE;

        #pragma unroll
        for (int kp = 0; kp < 2; kp++) {
            uint32_t a[4][4], b[8][2];
            #pragma unroll
            for (int mt = 0; mt < 4; mt++) {
                uint32_t base = sA + (warp_m * 64 + mt * 16 + qrow) * ROW_PAD + kp * 32 + qcol;
                a[mt][0] = lds32(base);
                a[mt][1] = lds32(base + 8 * ROW_PAD);
                a[mt][2] = lds32(base + 16);
                a[mt][3] = lds32(base + 8 * ROW_PAD + 16);
            }
            #pragma unroll
            for (int nt = 0; nt < 8; nt++) {
                uint32_t base = sB + (warp_n * 64 + nt * 8 + qrow) * ROW_PAD + kp * 32 + qcol;
                b[nt][0] = lds32(base);
                b[nt][1] = lds32(base + 16);
            }
            #pragma unroll
            for (int mt = 0; mt < 4; mt++)
                #pragma unroll
                for (int nt = 0; nt < 8; nt++)
                    imma16832(c[mt][nt], a[mt], b[nt]);
        }
        __syncthreads();
    }
    CP_WAIT0();

    // Epilogue: dequant + bias
    const float sx = __uint_as_float(g_amax_x) / 127.0f;
    const float sw = __uint_as_float(g_amax_w) / 127.0f;
    const float s = sx * sw;

    #pragma unroll
    for (int mt = 0; mt < 4; mt++) {
        #pragma unroll
        for (int half = 0; half < 2; half++) {
            int row = m0 + warp_m * 64 + mt * 16 + (lane >> 2) + half * 8;
            float* orow = out + (size_t)row * NN;
            #pragma unroll
            for (int nt = 0; nt < 8; nt++) {
                int col = n0 + warp_n * 64 + nt * 8 + (lane & 3) * 2;
                float2 o;
                o.x = (float)c[mt][nt][half * 2 + 0] * s + __ldg(&bias[col]);
                o.y = (float)c[mt][nt][half * 2 + 1] * s + __ldg(&bias[col + 1]);
                *reinterpret_cast<float2*>(orow + col) = o;
            }
        }
    }
}

// ============================================================================
// kernel_launch — graph-capturable, allocation-free
// ============================================================================
extern "C" void kernel_launch(void* const* d_in, const int* in_sizes, int n_in,
                              void* d_out, int out_size) {
    const float* x    = (const float*)d_in[0];   // [M, K]
    const float* w    = (const float*)d_in[1];   // [N, K]
    const float* bias = (const float*)d_in[2];   // [N]
    float* out        = (float*)d_out;           // [M, N]

    reset_kernel<<<1, 1>>>();
    absmax_kernel<<<2048, 256>>>(x, (long)MM * KK / 4, 0);
    absmax_kernel<<<1024, 256>>>(w, (long)NN * KK / 4, 1);
    quant_kernel<<<8192, 256>>>(x, (long)MM * KK / 4, 0);
    quant_kernel<<<4096, 256>>>(w, (long)NN * KK / 4, 1);

    static bool attr_set = false;
    if (!attr_set) {
        cudaFuncSetAttribute(gemm_kernel, cudaFuncAttributeMaxDynamicSharedMemorySize, SMEM_BYTES);
        attr_set = true;
    }
    gemm_kernel<<<dim3(NN / 128, MM / 128, 1), 128, SMEM_BYTES>>>(bias, out);
}

// round 5
// speedup vs baseline: 2.0892x; 2.0892x over previous
#include <cuda_runtime.h>
#include <cuda_bf16.h>
#include <cstdint>
#include <cstddef>

// ============================================================================
// Problem dims
// ============================================================================
#define MM 8192
#define KK 4096
#define NN 4096

// ============================================================================
// Device scratch (allowed: __device__ globals, no runtime allocation)
// ============================================================================
__device__ unsigned g_amax_x;
__device__ unsigned g_amax_w;
__device__ __nv_bfloat16 g_xq[(size_t)MM * KK];   // quantized activations (exact ints in bf16)
__device__ __nv_bfloat16 g_wq[(size_t)NN * KK];   // quantized weights

// ============================================================================
// PTX helpers — family-generic (sm_80+ PTX only; NO tcgen05 on this target!)
// ============================================================================
__device__ __forceinline__ uint32_t smem_u32(const void* p) {
    uint32_t a;
    asm("{ .reg .u64 t; cvta.to.shared.u64 t, %1; cvt.u32.u64 %0, t; }" : "=r"(a) : "l"(p));
    return a;
}

#define CP_ASYNC16(dst, src) \
    asm volatile("cp.async.cg.shared.global [%0], [%1], 16;" :: "r"(dst), "l"(src) : "memory")
#define CP_COMMIT() asm volatile("cp.async.commit_group;" ::: "memory")
#define CP_WAIT2()  asm volatile("cp.async.wait_group 2;" ::: "memory")
#define CP_WAIT0()  asm volatile("cp.async.wait_group 0;" ::: "memory")

// bf16 warp MMA: D(16x8,f32) = A(16x16,bf16,row) * B(16x8,bf16,col) + D
__device__ __forceinline__ void hmma16816(float* c, const uint32_t* a, const uint32_t* b) {
    asm volatile(
        "mma.sync.aligned.m16n8k16.row.col.f32.bf16.bf16.f32 "
        "{%0,%1,%2,%3}, {%4,%5,%6,%7}, {%8,%9}, {%0,%1,%2,%3};"
        : "+f"(c[0]), "+f"(c[1]), "+f"(c[2]), "+f"(c[3])
        : "r"(a[0]), "r"(a[1]), "r"(a[2]), "r"(a[3]), "r"(b[0]), "r"(b[1]));
}

__device__ __forceinline__ uint32_t lds32(uint32_t addr) {
    uint32_t v;
    asm volatile("ld.shared.b32 %0, [%1];" : "=r"(v) : "r"(addr));
    return v;
}

// ============================================================================
// Pass 1: reset + abs-max reductions
// ============================================================================
__global__ void reset_kernel() {
    g_amax_x = 0u;
    g_amax_w = 0u;
}

__global__ void absmax_kernel(const float* __restrict__ in, long n4, int which) {
    float m = 0.0f;
    long i = (long)blockIdx.x * blockDim.x + threadIdx.x;
    long stride = (long)gridDim.x * blockDim.x;
    const float4* in4 = reinterpret_cast<const float4*>(in);
    for (; i < n4; i += stride) {
        float4 v = in4[i];
        m = fmaxf(m, fmaxf(fmaxf(fabsf(v.x), fabsf(v.y)), fmaxf(fabsf(v.z), fabsf(v.w))));
    }
    #pragma unroll
    for (int o = 16; o > 0; o >>= 1)
        m = fmaxf(m, __shfl_xor_sync(0xFFFFFFFFu, m, o));
    if ((threadIdx.x & 31) == 0)
        atomicMax(which ? &g_amax_w : &g_amax_x, __float_as_uint(m));
}

// ============================================================================
// Pass 2: quantize — exact match to jnp: clip(rint(t/scale), ±127)
// Values are integers in [-127,127]: exactly representable in bf16.
// ============================================================================
__global__ void quant_kernel(const float* __restrict__ in, long n4, int which) {
    float amax = __uint_as_float(which ? g_amax_w : g_amax_x);
    float scale = amax / 127.0f;
    __nv_bfloat16* q = which ? g_wq : g_xq;
    long i = (long)blockIdx.x * blockDim.x + threadIdx.x;
    long stride = (long)gridDim.x * blockDim.x;
    const float4* in4 = reinterpret_cast<const float4*>(in);
    __nv_bfloat162* q2 = reinterpret_cast<__nv_bfloat162*>(q);
    for (; i < n4; i += stride) {
        float4 v = in4[i];
        float a = fminf(fmaxf(rintf(v.x / scale), -127.0f), 127.0f);
        float b = fminf(fmaxf(rintf(v.y / scale), -127.0f), 127.0f);
        float c = fminf(fmaxf(rintf(v.z / scale), -127.0f), 127.0f);
        float d = fminf(fmaxf(rintf(v.w / scale), -127.0f), 127.0f);
        q2[2 * i + 0] = __floats2bfloat162_rn(a, b);
        q2[2 * i + 1] = __floats2bfloat162_rn(c, d);
    }
}

// ============================================================================
// Pass 3: bf16 GEMM  out[M,N] = Xq[M,K] @ Wq[N,K]^T * s + bias
//   BM=128, BN=128, BK=32 (bf16) = 64B rows; 128 threads = 4 warps (64x64 each)
//   4-stage cp.async pipeline; SMEM rows padded 64B -> 80B (conflict-free)
//   Fragment addressing identical to the int8 BK=64 layout (2x k16 sub-steps).
// ============================================================================
static constexpr int BK = 32;                 // bf16 elems per K chunk (64B rows)
static constexpr int NKT = KK / BK;           // 128 k-tiles
static constexpr int ROW_PAD = 80;            // 64B data + 16B pad
static constexpr int A_STAGE = 128 * ROW_PAD; // 10240 B
static constexpr int STAGE_BYTES = 2 * A_STAGE; // A + B = 20480 B
static constexpr int NSTAGE = 4;
static constexpr int SMEM_BYTES = NSTAGE * STAGE_BYTES;  // 81920 B

__device__ __forceinline__ void stage_copy(uint32_t sbase, int kt, int m0, int n0, int tid) {
    const size_t kofs = (size_t)kt * BK;       // element offset
    #pragma unroll
    for (int i = 0; i < 4; i++) {
        int idx = tid + i * 128;               // 0..511
        int row = idx >> 2, ch = idx & 3;      // 4 x 16B chunks per 64B row
        CP_ASYNC16(sbase + row * ROW_PAD + ch * 16,
                   (const void*)(g_xq + (size_t)(m0 + row) * KK + kofs + ch * 8));
    }
    #pragma unroll
    for (int i = 0; i < 4; i++) {
        int idx = tid + i * 128;
        int row = idx >> 2, ch = idx & 3;
        CP_ASYNC16(sbase + A_STAGE + row * ROW_PAD + ch * 16,
                   (const void*)(g_wq + (size_t)(n0 + row) * KK + kofs + ch * 8));
    }
}

extern "C" __global__ void __launch_bounds__(128, 2)
gemm_kernel(const float* __restrict__ bias, float* __restrict__ out) {
    extern __shared__ char smem[];
    const uint32_t sb = smem_u32(smem);
    const int tid = threadIdx.x;
    const int wid = tid >> 5;
    const int lane = tid & 31;
    const int warp_m = wid & 1;          // 2 warps along M
    const int warp_n = wid >> 1;         // 2 warps along N
    const int m0 = blockIdx.y * 128;
    const int n0 = blockIdx.x * 128;

    float c[4][8][4];
    #pragma unroll
    for (int mt = 0; mt < 4; mt++)
        #pragma unroll
        for (int nt = 0; nt < 8; nt++)
            #pragma unroll
            for (int j = 0; j < 4; j++) c[mt][nt][j] = 0.0f;

    // Prologue: fill stages 0..2
    #pragma unroll
    for (int s = 0; s < NSTAGE - 1; s++) {
        stage_copy(sb + s * STAGE_BYTES, s, m0, n0, tid);
        CP_COMMIT();
    }

    const int qrow = lane >> 2;           // 0..7
    const int qcol = (lane & 3) * 4;      // byte offset (2 bf16 per 4B)

    for (int kt = 0; kt < NKT; kt++) {
        CP_WAIT2();
        __syncthreads();

        // Issue copy for stage kt+3 (that buffer's compute finished at kt-1).
        // Commit a (possibly empty) group each iter so wait_group 2 lands on kt.
        if (kt + NSTAGE - 1 < NKT)
            stage_copy(sb + ((kt + NSTAGE - 1) & (NSTAGE - 1)) * STAGE_BYTES,
                       kt + NSTAGE - 1, m0, n0, tid);
        CP_COMMIT();

        const uint32_t sA = sb + (kt & (NSTAGE - 1)) * STAGE_BYTES;
        const uint32_t sB = sA + A_STAGE;

        // Two k16 sub-steps within the 32-elem (64B) K chunk
        #pragma unroll
        for (int kp = 0; kp < 2; kp++) {
            uint32_t a[4][4], b[8][2];
            #pragma unroll
            for (int mt = 0; mt < 4; mt++) {
                // A frag m16n8k16 (row-major): a0 (r, k0-7), a1 (r+8, k0-7),
                // a2 (r, k8-15), a3 (r+8, k8-15); 16 elems = 32B per sub-step
                uint32_t base = sA + (warp_m * 64 + mt * 16 + qrow) * ROW_PAD + kp * 32 + qcol;
                a[mt][0] = lds32(base);
                a[mt][1] = lds32(base + 8 * ROW_PAD);
                a[mt][2] = lds32(base + 16);
                a[mt][3] = lds32(base + 8 * ROW_PAD + 16);
            }
            #pragma unroll
            for (int nt = 0; nt < 8; nt++) {
                // B frag (col-major = W rows): b0 (n, k0-7), b1 (n, k8-15)
                uint32_t base = sB + (warp_n * 64 + nt * 8 + qrow) * ROW_PAD + kp * 32 + qcol;
                b[nt][0] = lds32(base);
                b[nt][1] = lds32(base + 16);
            }
            #pragma unroll
            for (int mt = 0; mt < 4; mt++)
                #pragma unroll
                for (int nt = 0; nt < 8; nt++)
                    hmma16816(c[mt][nt], a[mt], b[nt]);
        }
        __syncthreads();
    }
    CP_WAIT0();

    // Epilogue: dequant + bias
    const float sx = __uint_as_float(g_amax_x) / 127.0f;
    const float sw = __uint_as_float(g_amax_w) / 127.0f;
    const float s = sx * sw;

    #pragma unroll
    for (int mt = 0; mt < 4; mt++) {
        #pragma unroll
        for (int half = 0; half < 2; half++) {
            int row = m0 + warp_m * 64 + mt * 16 + (lane >> 2) + half * 8;
            float* orow = out + (size_t)row * NN;
            #pragma unroll
            for (int nt = 0; nt < 8; nt++) {
                int col = n0 + warp_n * 64 + nt * 8 + (lane & 3) * 2;
                float2 o;
                o.x = c[mt][nt][half * 2 + 0] * s + __ldg(&bias[col]);
                o.y = c[mt][nt][half * 2 + 1] * s + __ldg(&bias[col + 1]);
                *reinterpret_cast<float2*>(orow + col) = o;
            }
        }
    }
}

// ============================================================================
// kernel_launch — graph-capturable, allocation-free
// ============================================================================
extern "C" void kernel_launch(void* const* d_in, const int* in_sizes, int n_in,
                              void* d_out, int out_size) {
    const float* x    = (const float*)d_in[0];   // [M, K]
    const float* w    = (const float*)d_in[1];   // [N, K]
    const float* bias = (const float*)d_in[2];   // [N]
    float* out        = (float*)d_out;           // [M, N]

    reset_kernel<<<1, 1>>>();
    absmax_kernel<<<2048, 256>>>(x, (long)MM * KK / 4, 0);
    absmax_kernel<<<1024, 256>>>(w, (long)NN * KK / 4, 1);
    quant_kernel<<<8192, 256>>>(x, (long)MM * KK / 4, 0);
    quant_kernel<<<4096, 256>>>(w, (long)NN * KK / 4, 1);

    static bool attr_set = false;
    if (!attr_set) {
        cudaFuncSetAttribute(gemm_kernel, cudaFuncAttributeMaxDynamicSharedMemorySize, SMEM_BYTES);
        attr_set = true;
    }
    gemm_kernel<<<dim3(NN / 128, MM / 128, 1), 128, SMEM_BYTES>>>(bias, out);
}